// round 14
// baseline (speedup 1.0000x reference)
#include <cuda_runtime.h>
#include <cuda_bf16.h>
#include <cuda_fp16.h>
#include <cstdint>

// ---------------- problem constants (fixed shapes) ----------------
#define NNODES 50000
#define NEDGES 400000
#define HID    64
#define NREL   230
#define NTS    365
#define NPAIR  (NREL * NTS)      // 83950
#define DIM    128               // 2*HID
#define SLOPE  0.2f

#define NB0 782                  // 2 * ceil(50000/128) mode-0 CTAs
#define NB1 657                  // ceil(83950/128)     mode-1 CTAs
#define NBLK ((NNODES + 255) / 256)   // 196 scan blocks

// ---------------- device scratch (static; no runtime alloc) -------
__device__ __align__(16) float d_relpart[NREL * DIM];
__device__ __align__(16) float d_timepart[NTS * DIM];
__device__ __align__(16) __half d_P1h[NNODES * DIM];      // x@W1 (fp16, gathered per edge)
__device__ __align__(16) float  d_P3[NNODES * DIM];       // x@W3 (fp32, once per node)
__device__ __align__(16) __half d_rtbh[NPAIR * DIM];      // V@W2 (fp16, gathered per edge)
__device__ __align__(16) __nv_bfloat16 d_bT_hi[2 * DIM * DIM];   // [W1|W3]^T : [256][128]
__device__ __align__(16) __nv_bfloat16 d_bT_lo[2 * DIM * DIM];
__device__ __align__(16) __nv_bfloat16 d_w2T_hi[DIM * DIM];      // W2^T : [128][128]
__device__ __align__(16) __nv_bfloat16 d_w2T_lo[DIM * DIM];
__device__ int d_counts[NNODES];
__device__ int d_bsums[NBLK];
__device__ int d_offsets[NNODES + 1];
__device__ int d_cursor[NNODES];
__device__ int d_ssrc[NEDGES];
__device__ int d_spair[NEDGES];

__device__ __forceinline__ float lrelu(float v) {
    return v >= 0.0f ? v : SLOPE * v;
}

__device__ __forceinline__ uint32_t smem_u32(const void* p) {
    uint32_t a;
    asm("{ .reg .u64 t; cvta.to.shared.u64 t, %1; cvt.u32.u64 %0, t; }"
        : "=r"(a) : "l"(p));
    return a;
}

__device__ __forceinline__ void ldsm4(uint32_t* r, uint32_t addr) {
    asm volatile("ldmatrix.sync.aligned.m8n8.x4.shared.b16 {%0,%1,%2,%3}, [%4];"
                 : "=r"(r[0]), "=r"(r[1]), "=r"(r[2]), "=r"(r[3]) : "r"(addr));
}

__device__ __forceinline__ void mma_bf16(float* d, const uint32_t* a, const uint32_t* b) {
    asm volatile(
        "mma.sync.aligned.m16n8k16.row.col.f32.bf16.bf16.f32 "
        "{%0,%1,%2,%3}, {%4,%5,%6,%7}, {%8,%9}, {%0,%1,%2,%3};"
        : "+f"(d[0]), "+f"(d[1]), "+f"(d[2]), "+f"(d[3])
        : "r"(a[0]), "r"(a[1]), "r"(a[2]), "r"(a[3]), "r"(b[0]), "r"(b[1]));
}

__device__ __forceinline__ void cpa16(uint32_t dst, const void* src, int srcsize) {
    asm volatile("cp.async.cg.shared.global [%0], [%1], 16, %2;"
                 :: "r"(dst), "l"(src), "r"(srcsize));
}
#define CPA_COMMIT() asm volatile("cp.async.commit_group;" ::: "memory")
#define CPA_WAIT0()  asm volatile("cp.async.wait_group 0;" ::: "memory")

// ---------------- split helpers ------------------------------------
__device__ __forceinline__ void bf16_split(float v, __nv_bfloat16& hi, __nv_bfloat16& lo) {
    hi = __float2bfloat16_rn(v);
    lo = __float2bfloat16_rn(v - __bfloat162float(hi));
}

// ---------------- merged prep: proj + weight transpose/split ------
__global__ void k_prep(const float* __restrict__ rel_table,
                       const float* __restrict__ time_table,
                       const float* __restrict__ W_rt,
                       const float* __restrict__ W_fc) {
    int b = blockIdx.x;
    int tid = threadIdx.x;
    if (b < NREL + NTS) {
        if (tid >= DIM) return;
        int j = tid;
        float acc = 0.0f;
        if (b < NREL) {
            const float* a = rel_table + b * HID;
#pragma unroll
        for (int k = 0; k < HID; k++) acc += a[k] * W_rt[k * DIM + j];
            d_relpart[b * DIM + j] = acc;
        } else {
            int r = b - NREL;
            const float* a = time_table + r * HID;
#pragma unroll
            for (int k = 0; k < HID; k++) acc += a[k] * W_rt[(HID + k) * DIM + j];
            d_timepart[r * DIM + j] = acc;
        }
    } else {
        int idx = (b - (NREL + NTS)) * 256 + tid;
        if (idx < 2 * DIM * DIM) {
            int n = idx >> 7, k = idx & 127;
            float v = (n < DIM) ? W_fc[k * DIM + n]
                                : W_fc[(2 * DIM + k) * DIM + (n - DIM)];
            __nv_bfloat16 h, l; bf16_split(v, h, l);
            d_bT_hi[idx] = h; d_bT_lo[idx] = l;
        } else if (idx < 3 * DIM * DIM) {
            int j = idx - 2 * DIM * DIM;
            int n = j >> 7, k = j & 127;
            float v = W_fc[(DIM + k) * DIM + n];
            __nv_bfloat16 h, l; bf16_split(v, h, l);
            d_w2T_hi[j] = h; d_w2T_lo[j] = l;
        }
    }
}

// ---------------- HMMA bf16x3 GEMM: resident B + overlapped convert
#define PITCH  40    // A smem: halves per row (80B), conflict-free ldmatrix
#define PITCHB 136   // B smem: halves per row (272B = 17*16), conflict-free

// dynamic smem layout (bytes):
//   ABUF(b) (b=0,1): Ah at b*20480, Al at b*20480 + 10240    -> 40960
//   Bh at 40960 (128*136*2 = 34816), Bl at 75776             -> 69632
#define OFF_A(b) ((b) * 20480)
#define OFF_BH   40960
#define OFF_BL   75776
#define SM_TOTAL 110592

__global__ __launch_bounds__(256, 2) void hmma_all(
    const float* __restrict__ x,
    const float* __restrict__ b_rt)
{
    extern __shared__ char smem[];
    const uint32_t sbase = smem_u32(smem);

    const int tid = threadIdx.x;
    const int wid = tid >> 5;
    const int lane = tid & 31;
    const int bid = blockIdx.x;

    const bool m0 = (bid < NB0);
    int bm, bn, M;
    const __nv_bfloat16 *Bh_, *Bl_;
    if (m0) {
        bm = (bid >> 1) * 128; bn = (bid & 1) * 128;
        Bh_ = d_bT_hi; Bl_ = d_bT_lo; M = NNODES;
    } else {
        int b2 = bid - NB0;
        bm = b2 * 128; bn = 0;
        Bh_ = d_w2T_hi; Bl_ = d_w2T_lo; M = NPAIR;
    }

    const int wm = (wid & 3) * 32;
    const int wn = (wid >> 2) * 64;

    float acc[2][8][4];
#pragma unroll
    for (int i = 0; i < 2; i++)
#pragma unroll
        for (int j = 0; j < 8; j++)
#pragma unroll
            for (int k = 0; k < 4; k++) acc[i][j][k] = 0.0f;

    const int a_c = (tid & 7) * 4;        // convert: float4 col within 32-chunk
    const int a_r0 = tid >> 3;            // rows a_r0 + 32*j

    // convert chunk cc: build Ah/Al[cc&1] from fp32 source via LDG
    auto convert = [&](int cc) {
        const int k0 = cc * 32;
        const uint32_t abase = sbase + OFF_A(cc & 1);
#pragma unroll
        for (int j = 0; j < 4; j++) {
            int row = a_r0 + j * 32;
            int grow = bm + row;
            float4 v = make_float4(0.f, 0.f, 0.f, 0.f);
            if (m0) {
                if (grow < M)
                    v = *reinterpret_cast<const float4*>(x + (size_t)grow * DIM + k0 + a_c);
            } else {
                if (grow < M) {
                    int r = grow / NTS;
                    int t = grow - r * NTS;
                    float4 rv = *reinterpret_cast<const float4*>(&d_relpart[r * DIM + k0 + a_c]);
                    float4 tv = *reinterpret_cast<const float4*>(&d_timepart[t * DIM + k0 + a_c]);
                    float4 bv = *reinterpret_cast<const float4*>(&b_rt[k0 + a_c]);
                    v.x = lrelu(rv.x + tv.x + bv.x);
                    v.y = lrelu(rv.y + tv.y + bv.y);
                    v.z = lrelu(rv.z + tv.z + bv.z);
                    v.w = lrelu(rv.w + tv.w + bv.w);
                }
            }
            __nv_bfloat16 h[4], l[4];
            bf16_split(v.x, h[0], l[0]); bf16_split(v.y, h[1], l[1]);
            bf16_split(v.z, h[2], l[2]); bf16_split(v.w, h[3], l[3]);
            __nv_bfloat16* ph = reinterpret_cast<__nv_bfloat16*>(smem) +
                                (OFF_A(cc & 1) >> 1) + row * PITCH + a_c;
            __nv_bfloat16* pl = ph + (10240 >> 1);
            *reinterpret_cast<__nv_bfloat162*>(ph)     = __nv_bfloat162(h[0], h[1]);
            *reinterpret_cast<__nv_bfloat162*>(ph + 2) = __nv_bfloat162(h[2], h[3]);
            *reinterpret_cast<__nv_bfloat162*>(pl)     = __nv_bfloat162(l[0], l[1]);
            *reinterpret_cast<__nv_bfloat162*>(pl + 2) = __nv_bfloat162(l[2], l[3]);
        }
        (void)abase;
    };

    // ---- prologue: full B tile via cp.async (resident all 4 chunks) ----
#pragma unroll
    for (int j = 0; j < 8; j++) {
        int u = tid + 256 * j;
        int r = u >> 4;
        int c = (u & 15) * 8;             // halves (16B granule)
        uint32_t so = (uint32_t)(r * PITCHB + c) * 2;
        cpa16(sbase + OFF_BH + so, Bh_ + (size_t)(bn + r) * DIM + c, 16);
        cpa16(sbase + OFF_BL + so, Bl_ + (size_t)(bn + r) * DIM + c, 16);
    }
    CPA_COMMIT();
    convert(0);                            // overlaps the B cp.async
    CPA_WAIT0();
    __syncthreads();                       // B + ABUF0 visible to all

    // ---- mainloop: convert(j+1) overlapped with MMA(j), 1 sync/chunk ----
    for (int j = 0; j < 4; j++) {
        if (j < 3) convert(j + 1);         // writes ABUF((j+1)&1); MMA reads ABUF(j&1)

        const uint32_t uAh = sbase + OFF_A(j & 1);
        const uint32_t uAl = uAh + 10240;
        const int kbase = j * 32;
#pragma unroll
        for (int ks = 0; ks < 2; ks++) {
            uint32_t ah[2][4], al[2][4];
#pragma unroll
            for (int mt = 0; mt < 2; mt++) {
                int row = wm + mt * 16 + (lane & 15);
                int koff = ks * 16 + ((lane >> 4) << 3);
                uint32_t off = (uint32_t)(row * PITCH + koff) * 2;
                ldsm4(ah[mt], uAh + off);
                ldsm4(al[mt], uAl + off);
            }
#pragma unroll
            for (int np = 0; np < 4; np++) {
                int mat = lane >> 3;
                int row = wn + np * 16 + ((mat >> 1) << 3) + (lane & 7);
                int koff = kbase + ks * 16 + ((mat & 1) << 3);
                uint32_t off = (uint32_t)(row * PITCHB + koff) * 2;
                uint32_t bh[4], bl[4];
                ldsm4(bh, sbase + OFF_BH + off);
                ldsm4(bl, sbase + OFF_BL + off);
#pragma unroll
                for (int mt = 0; mt < 2; mt++) {
                    mma_bf16(acc[mt][np * 2],     ah[mt], &bh[0]);
                    mma_bf16(acc[mt][np * 2],     ah[mt], &bl[0]);
                    mma_bf16(acc[mt][np * 2],     al[mt], &bh[0]);
                    mma_bf16(acc[mt][np * 2 + 1], ah[mt], &bh[2]);
                    mma_bf16(acc[mt][np * 2 + 1], ah[mt], &bl[2]);
                    mma_bf16(acc[mt][np * 2 + 1], al[mt], &bh[2]);
                }
            }
        }
        __syncthreads();                   // protects ABUF reuse next iteration
    }

    // epilogue: P1 (fp16), P3 (fp32), rtb (fp16); all ld = 128
    const int tr = lane >> 2;
    const int tc = (lane & 3) * 2;
    const bool toP3 = (m0 && bn == 128);
    __half* Ch = m0 ? d_P1h : d_rtbh;
#pragma unroll
    for (int mt = 0; mt < 2; mt++) {
        int grow0 = bm + wm + mt * 16 + tr;
        int grow1 = grow0 + 8;
#pragma unroll
        for (int nt = 0; nt < 8; nt++) {
            int lcol = wn + nt * 8 + tc;
            if (toP3) {
                if (grow0 < M)
                    *reinterpret_cast<float2*>(&d_P3[(size_t)grow0 * DIM + lcol]) =
                        make_float2(acc[mt][nt][0], acc[mt][nt][1]);
                if (grow1 < M)
                    *reinterpret_cast<float2*>(&d_P3[(size_t)grow1 * DIM + lcol]) =
                        make_float2(acc[mt][nt][2], acc[mt][nt][3]);
            } else {
                if (grow0 < M)
                    *reinterpret_cast<__half2*>(&Ch[(size_t)grow0 * DIM + lcol]) =
                        __floats2half2_rn(acc[mt][nt][0], acc[mt][nt][1]);
                if (grow1 < M)
                    *reinterpret_cast<__half2*>(&Ch[(size_t)grow1 * DIM + lcol]) =
                        __floats2half2_rn(acc[mt][nt][2], acc[mt][nt][3]);
            }
        }
    }
}

// ---------------- counting sort by dst -----------------------------
__global__ void k_count(const int* __restrict__ edges) {
    int e = blockIdx.x * blockDim.x + threadIdx.x;
    if (e >= NEDGES) return;
    int4 ed = reinterpret_cast<const int4*>(edges)[e];
    atomicAdd(&d_counts[ed.y], 1);
}

// ---- two-level scan: block sums -> scan sums -> final offsets ----
__global__ __launch_bounds__(256) void k_bsum() {
    int i = blockIdx.x * 256 + threadIdx.x;
    int lane = threadIdx.x & 31, w = threadIdx.x >> 5;
    int v = (i < NNODES) ? d_counts[i] : 0;
#pragma unroll
    for (int o = 16; o > 0; o >>= 1) v += __shfl_down_sync(0xFFFFFFFFu, v, o);
    __shared__ int ws[8];
    if (lane == 0) ws[w] = v;
    __syncthreads();
    if (threadIdx.x == 0) {
        int s = 0;
#pragma unroll
        for (int j = 0; j < 8; j++) s += ws[j];
        d_bsums[blockIdx.x] = s;
    }
}

__global__ __launch_bounds__(256) void k_scanb() {
    int t = threadIdx.x;
    int lane = t & 31, w = t >> 5;
    int v = (t < NBLK) ? d_bsums[t] : 0;
    int inc = v;
#pragma unroll
    for (int o = 1; o < 32; o <<= 1) {
        int u = __shfl_up_sync(0xFFFFFFFFu, inc, o);
        if (lane >= o) inc += u;
    }
    __shared__ int ws[8];
    if (lane == 31) ws[w] = inc;
    __syncthreads();
    if (w == 0 && lane < 8) {
        int s = ws[lane];
#pragma unroll
        for (int o = 1; o < 8; o <<= 1) {
            int u = __shfl_up_sync(0xFFu, s, o);
            if (lane >= o) s += u;
        }
        ws[lane] = s;
    }
    __syncthreads();
    int excl = inc - v + (w > 0 ? ws[w - 1] : 0);
    if (t < NBLK) d_bsums[t] = excl;
}

__global__ __launch_bounds__(256) void k_scanfin() {
    int b = blockIdx.x;
    int i = b * 256 + threadIdx.x;
    int lane = threadIdx.x & 31, w = threadIdx.x >> 5;
    int v = (i < NNODES) ? d_counts[i] : 0;
    int inc = v;
#pragma unroll
    for (int o = 1; o < 32; o <<= 1) {
        int u = __shfl_up_sync(0xFFFFFFFFu, inc, o);
        if (lane >= o) inc += u;
    }
    __shared__ int ws[8];
    if (lane == 31) ws[w] = inc;
    __syncthreads();
    if (w == 0 && lane < 8) {
        int s = ws[lane];
#pragma unroll
        for (int o = 1; o < 8; o <<= 1) {
            int u = __shfl_up_sync(0xFFu, s, o);
            if (lane >= o) s += u;
        }
        ws[lane] = s;
    }
    __syncthreads();
    int excl = inc - v + (w > 0 ? ws[w - 1] : 0) + d_bsums[b];
    if (i < NNODES) {
        d_offsets[i] = excl;
        d_cursor[i] = excl;
        if (i == NNODES - 1) d_offsets[NNODES] = excl + v;
    }
}

__global__ void k_scatter(const int* __restrict__ edges) {
    int e = blockIdx.x * blockDim.x + threadIdx.x;
    if (e >= NEDGES) return;
    int4 ed = reinterpret_cast<const int4*>(edges)[e];
    int pos = atomicAdd(&d_cursor[ed.y], 1);
    d_ssrc[pos] = ed.x;
    d_spair[pos] = ed.z * NTS + ed.w;
}

// ---------------- aggregation: warp per node, fp16 gathers, x4 ----
__device__ __forceinline__ void agg_accum(uint2 a, uint2 r, const float4& c3,
                                          float& ax, float& ay, float& az, float& aw) {
    float2 alo = __half22float2(*reinterpret_cast<const __half2*>(&a.x));
    float2 ahi = __half22float2(*reinterpret_cast<const __half2*>(&a.y));
    float2 rlo = __half22float2(*reinterpret_cast<const __half2*>(&r.x));
    float2 rhi = __half22float2(*reinterpret_cast<const __half2*>(&r.y));
    ax += lrelu(alo.x + rlo.x + c3.x);
    ay += lrelu(alo.y + rlo.y + c3.y);
    az += lrelu(ahi.x + rhi.x + c3.z);
    aw += lrelu(ahi.y + rhi.y + c3.w);
}

__global__ __launch_bounds__(256) void k_agg(float* __restrict__ out,
                                             const float* __restrict__ b_fc) {
    int warp = (blockIdx.x * blockDim.x + threadIdx.x) >> 5;
    int lane = threadIdx.x & 31;
    if (warp >= NNODES) return;

    int s0 = d_offsets[warp];
    int s1 = d_offsets[warp + 1];

    const uint2* P1 = reinterpret_cast<const uint2*>(d_P1h);
    const uint2* R  = reinterpret_cast<const uint2*>(d_rtbh);
    const float4* P3 = reinterpret_cast<const float4*>(d_P3);

    float4 bias4 = reinterpret_cast<const float4*>(b_fc)[lane];
    float4 c3 = P3[warp * 32 + lane];
    c3.x += bias4.x; c3.y += bias4.y; c3.z += bias4.z; c3.w += bias4.w;

    float ax = 0.f, ay = 0.f, az = 0.f, aw = 0.f;
    int i = s0;
    for (; i + 4 <= s1; i += 4) {
        int sA = __ldg(&d_ssrc[i]);
        int sB = __ldg(&d_ssrc[i + 1]);
        int sC = __ldg(&d_ssrc[i + 2]);
        int sD = __ldg(&d_ssrc[i + 3]);
        int pA = __ldg(&d_spair[i]);
        int pB = __ldg(&d_spair[i + 1]);
        int pC = __ldg(&d_spair[i + 2]);
        int pD = __ldg(&d_spair[i + 3]);
        uint2 a0 = __ldg(&P1[sA * 32 + lane]);
        uint2 r0 = __ldg(&R[pA * 32 + lane]);
        uint2 a1 = __ldg(&P1[sB * 32 + lane]);
        uint2 r1 = __ldg(&R[pB * 32 + lane]);
        uint2 a2 = __ldg(&P1[sC * 32 + lane]);
        uint2 r2 = __ldg(&R[pC * 32 + lane]);
        uint2 a3 = __ldg(&P1[sD * 32 + lane]);
        uint2 r3 = __ldg(&R[pD * 32 + lane]);
        agg_accum(a0, r0, c3, ax, ay, az, aw);
        agg_accum(a1, r1, c3, ax, ay, az, aw);
        agg_accum(a2, r2, c3, ax, ay, az, aw);
        agg_accum(a3, r3, c3, ax, ay, az, aw);
    }
    for (; i < s1; i++) {
        int s = __ldg(&d_ssrc[i]);
        int pr = __ldg(&d_spair[i]);
        uint2 a0 = __ldg(&P1[s * 32 + lane]);
        uint2 r0 = __ldg(&R[pr * 32 + lane]);
        agg_accum(a0, r0, c3, ax, ay, az, aw);
    }
    int cnt = s1 - s0;
    float inv = 1.0f / (float)(cnt > 0 ? cnt : 1);
    float4 r;
    r.x = ax * inv; r.y = ay * inv; r.z = az * inv; r.w = aw * inv;
    reinterpret_cast<float4*>(out)[warp * 32 + lane] = r;
}

// ---------------- launcher ----------------------------------------
extern "C" void kernel_launch(void* const* d_in, const int* in_sizes, int n_in,
                              void* d_out, int out_size) {
    const float* x          = (const float*)d_in[0];
    const float* rel_table  = (const float*)d_in[1];
    const float* time_table = (const float*)d_in[2];
    const float* W_rt       = (const float*)d_in[3];
    const float* b_rt       = (const float*)d_in[4];
    const float* W_fc       = (const float*)d_in[5];
    const float* b_fc       = (const float*)d_in[6];
    const int*   edges      = (const int*)d_in[7];
    float* out = (float*)d_out;

    cudaFuncSetAttribute(hmma_all, cudaFuncAttributeMaxDynamicSharedMemorySize, SM_TOTAL);

    // side stream + fork/join events (created once, before first capture)
    static cudaStream_t s1 = nullptr;
    static cudaEvent_t evFork = nullptr, evJoin = nullptr;
    if (!s1) {
        cudaStreamCreateWithFlags(&s1, cudaStreamNonBlocking);
        cudaEventCreateWithFlags(&evFork, cudaEventDisableTiming);
        cudaEventCreateWithFlags(&evJoin, cudaEventDisableTiming);
    }

    void* pCounts;
    cudaGetSymbolAddress(&pCounts, d_counts);

    // ---- fork: sort chain on side stream, GEMM chain on main ----
    cudaEventRecord(evFork, 0);
    cudaStreamWaitEvent(s1, evFork, 0);

    cudaMemsetAsync(pCounts, 0, NNODES * sizeof(int), s1);
    k_count<<<(NEDGES + 255) / 256, 256, 0, s1>>>(edges);
    k_bsum<<<NBLK, 256, 0, s1>>>();
    k_scanb<<<1, 256, 0, s1>>>();
    k_scanfin<<<NBLK, 256, 0, s1>>>();
    k_scatter<<<(NEDGES + 255) / 256, 256, 0, s1>>>(edges);
    cudaEventRecord(evJoin, s1);

    // main stream: prep + both GEMMs
    k_prep<<<NREL + NTS + 192, 256>>>(rel_table, time_table, W_rt, W_fc);
    hmma_all<<<NB0 + NB1, 256, SM_TOTAL>>>(x, b_rt);

    // ---- join: aggregation needs both chains ----
    cudaStreamWaitEvent(0, evJoin, 0);
    k_agg<<<(NNODES * 32 + 255) / 256, 256>>>(out, b_fc);
}

// round 15
// speedup vs baseline: 1.0812x; 1.0812x over previous
#include <cuda_runtime.h>
#include <cuda_bf16.h>
#include <cuda_fp16.h>
#include <cstdint>

// ---------------- problem constants (fixed shapes) ----------------
#define NNODES 50000
#define NEDGES 400000
#define HID    64
#define NREL   230
#define NTS    365
#define NPAIR  (NREL * NTS)      // 83950
#define DIM    128               // 2*HID
#define SLOPE  0.2f

#define NB0 782                  // 2 * ceil(50000/128) mode-0 CTAs
#define NB1 657                  // ceil(83950/128)     mode-1 CTAs
#define NBLK ((NNODES + 255) / 256)   // 196 scan blocks

// ---------------- device scratch (static; no runtime alloc) -------
__device__ __align__(16) float d_relpart[NREL * DIM];
__device__ __align__(16) float d_timepart[NTS * DIM];
__device__ __align__(16) __half d_P1h[NNODES * DIM];      // x@W1 (fp16, gathered per edge)
__device__ __align__(16) float  d_P3[NNODES * DIM];       // x@W3 (fp32, once per node)
__device__ __align__(16) __half d_rtbh[NPAIR * DIM];      // V@W2 (fp16, gathered per edge)
__device__ __align__(16) __nv_bfloat16 d_bT_hi[2 * DIM * DIM];   // [W1|W3]^T : [256][128]
__device__ __align__(16) __nv_bfloat16 d_bT_lo[2 * DIM * DIM];
__device__ __align__(16) __nv_bfloat16 d_w2T_hi[DIM * DIM];      // W2^T : [128][128]
__device__ __align__(16) __nv_bfloat16 d_w2T_lo[DIM * DIM];
__device__ int d_counts[NNODES];
__device__ int d_bsums[NBLK];
__device__ int d_offsets[NNODES + 1];
__device__ int d_cursor[NNODES];
__device__ int d_ssrc[NEDGES];
__device__ int d_spair[NEDGES];

__device__ __forceinline__ float lrelu(float v) {
    return v >= 0.0f ? v : SLOPE * v;
}

__device__ __forceinline__ uint32_t smem_u32(const void* p) {
    uint32_t a;
    asm("{ .reg .u64 t; cvta.to.shared.u64 t, %1; cvt.u32.u64 %0, t; }"
        : "=r"(a) : "l"(p));
    return a;
}

__device__ __forceinline__ void ldsm4(uint32_t* r, uint32_t addr) {
    asm volatile("ldmatrix.sync.aligned.m8n8.x4.shared.b16 {%0,%1,%2,%3}, [%4];"
                 : "=r"(r[0]), "=r"(r[1]), "=r"(r[2]), "=r"(r[3]) : "r"(addr));
}

__device__ __forceinline__ void mma_bf16(float* d, const uint32_t* a, const uint32_t* b) {
    asm volatile(
        "mma.sync.aligned.m16n8k16.row.col.f32.bf16.bf16.f32 "
        "{%0,%1,%2,%3}, {%4,%5,%6,%7}, {%8,%9}, {%0,%1,%2,%3};"
        : "+f"(d[0]), "+f"(d[1]), "+f"(d[2]), "+f"(d[3])
        : "r"(a[0]), "r"(a[1]), "r"(a[2]), "r"(a[3]), "r"(b[0]), "r"(b[1]));
}

__device__ __forceinline__ void cpa16(uint32_t dst, const void* src, int srcsize) {
    asm volatile("cp.async.cg.shared.global [%0], [%1], 16, %2;"
                 :: "r"(dst), "l"(src), "r"(srcsize));
}
#define CPA_COMMIT() asm volatile("cp.async.commit_group;" ::: "memory")
#define CPA_WAIT0()  asm volatile("cp.async.wait_group 0;" ::: "memory")

// ---------------- split helpers ------------------------------------
__device__ __forceinline__ void bf16_split(float v, __nv_bfloat16& hi, __nv_bfloat16& lo) {
    hi = __float2bfloat16_rn(v);
    lo = __float2bfloat16_rn(v - __bfloat162float(hi));
}

// ---------------- merged prep: proj + weight transpose/split ------
__global__ void k_prep(const float* __restrict__ rel_table,
                       const float* __restrict__ time_table,
                       const float* __restrict__ W_rt,
                       const float* __restrict__ W_fc) {
    int b = blockIdx.x;
    int tid = threadIdx.x;
    if (b < NREL + NTS) {
        if (tid >= DIM) return;
        int j = tid;
        float acc = 0.0f;
        if (b < NREL) {
            const float* a = rel_table + b * HID;
#pragma unroll
            for (int k = 0; k < HID; k++) acc += a[k] * W_rt[k * DIM + j];
            d_relpart[b * DIM + j] = acc;
        } else {
            int r = b - NREL;
            const float* a = time_table + r * HID;
#pragma unroll
            for (int k = 0; k < HID; k++) acc += a[k] * W_rt[(HID + k) * DIM + j];
            d_timepart[r * DIM + j] = acc;
        }
    } else {
        int idx = (b - (NREL + NTS)) * 256 + tid;
        if (idx < 2 * DIM * DIM) {
            int n = idx >> 7, k = idx & 127;
            float v = (n < DIM) ? W_fc[k * DIM + n]
                                : W_fc[(2 * DIM + k) * DIM + (n - DIM)];
            __nv_bfloat16 h, l; bf16_split(v, h, l);
            d_bT_hi[idx] = h; d_bT_lo[idx] = l;
        } else if (idx < 3 * DIM * DIM) {
            int j = idx - 2 * DIM * DIM;
            int n = j >> 7, k = j & 127;
            float v = W_fc[(DIM + k) * DIM + n];
            __nv_bfloat16 h, l; bf16_split(v, h, l);
            d_w2T_hi[j] = h; d_w2T_lo[j] = l;
        }
    }
}

// ---------------- merged, pipelined HMMA bf16x3 GEMM (R13 proven) --
#define PITCH 40   // halves per smem row (80B): conflict-free ldmatrix, 16B-aligned

// dynamic smem layout (bytes)
#define OFF_AH   0
#define OFF_AL   10240
#define OFF_BH0  20480
#define OFF_BL0  40960
#define OFF_ARAW 61440
#define SM_TOTAL 77824
#define BUFSZ    10240

__global__ __launch_bounds__(256, 2) void hmma_all(
    const float* __restrict__ x,
    const float* __restrict__ b_rt)
{
    extern __shared__ char smem[];
    const uint32_t sbase = smem_u32(smem);
    const uint32_t uAh = sbase + OFF_AH;
    const uint32_t uAl = sbase + OFF_AL;
    const uint32_t uAraw = sbase + OFF_ARAW;

    const int tid = threadIdx.x;
    const int wid = tid >> 5;
    const int lane = tid & 31;
    const int bid = blockIdx.x;

    const bool m0 = (bid < NB0);
    int bm, bn, M;
    const __nv_bfloat16 *Bh_, *Bl_;
    if (m0) {
        bm = (bid >> 1) * 128; bn = (bid & 1) * 128;
        Bh_ = d_bT_hi; Bl_ = d_bT_lo; M = NNODES;
    } else {
        int b2 = bid - NB0;
        bm = b2 * 128; bn = 0;
        Bh_ = d_w2T_hi; Bl_ = d_w2T_lo; M = NPAIR;
    }

    const int wm = (wid & 3) * 32;
    const int wn = (wid >> 2) * 64;

    float acc[2][8][4];
#pragma unroll
    for (int i = 0; i < 2; i++)
#pragma unroll
        for (int j = 0; j < 8; j++)
#pragma unroll
            for (int k = 0; k < 4; k++) acc[i][j][k] = 0.0f;

    const int a_c = (tid & 7) * 4;
    const int a_r0 = tid >> 3;
    const int b_c = (tid & 3) * 8;
    const int b_r0 = tid >> 2;

    auto issueB = [&](int k0, int buf) {
        uint32_t dBh = sbase + OFF_BH0 + buf * BUFSZ;
        uint32_t dBl = sbase + OFF_BL0 + buf * BUFSZ;
#pragma unroll
        for (int j = 0; j < 2; j++) {
            int row = b_r0 + j * 64;
            uint32_t so = (uint32_t)(row * PITCH + b_c) * 2;
            const __nv_bfloat16* gh = Bh_ + (bn + row) * DIM + k0 + b_c;
            const __nv_bfloat16* gl = Bl_ + (bn + row) * DIM + k0 + b_c;
            cpa16(dBh + so, gh, 16);
            cpa16(dBl + so, gl, 16);
        }
    };
    auto issueA = [&](int k0) {
        if (!m0) return;
#pragma unroll
        for (int j = 0; j < 4; j++) {
            int u = tid + 256 * j;
            int row = u >> 3;
            int cg = (u & 7) * 4;
            int grow = bm + row;
            int ok = (grow < M) ? 16 : 0;
            int gr = (grow < M) ? grow : (M - 1);
            cpa16(uAraw + (uint32_t)(row * 32 + cg) * 4,
                  x + (size_t)gr * DIM + k0 + cg, ok);
        }
    };

    issueA(0);
    issueB(0, 0);
    CPA_COMMIT();

    for (int i = 0; i < 4; i++) {
        const int k0 = i * 32;
        CPA_WAIT0();
        __syncthreads();

#pragma unroll
        for (int j = 0; j < 4; j++) {
            int row = a_r0 + j * 32;
            float4 v;
            if (m0) {
                v = *reinterpret_cast<const float4*>(
                        smem + OFF_ARAW + (size_t)(row * 32 + a_c) * 4);
            } else {
                int grow = bm + row;
                v = make_float4(0.f, 0.f, 0.f, 0.f);
                if (grow < M) {
                    int r = grow / NTS;
                    int t = grow - r * NTS;
                    float4 rv = *reinterpret_cast<const float4*>(&d_relpart[r * DIM + k0 + a_c]);
                    float4 tv = *reinterpret_cast<const float4*>(&d_timepart[t * DIM + k0 + a_c]);
                    float4 bv = *reinterpret_cast<const float4*>(&b_rt[k0 + a_c]);
                    v.x = lrelu(rv.x + tv.x + bv.x);
                    v.y = lrelu(rv.y + tv.y + bv.y);
                    v.z = lrelu(rv.z + tv.z + bv.z);
                    v.w = lrelu(rv.w + tv.w + bv.w);
                }
            }
            __nv_bfloat16 h[4], l[4];
            bf16_split(v.x, h[0], l[0]); bf16_split(v.y, h[1], l[1]);
            bf16_split(v.z, h[2], l[2]); bf16_split(v.w, h[3], l[3]);
            __nv_bfloat16* ph = reinterpret_cast<__nv_bfloat16*>(smem + OFF_AH) + row * PITCH + a_c;
            __nv_bfloat16* pl = reinterpret_cast<__nv_bfloat16*>(smem + OFF_AL) + row * PITCH + a_c;
            *reinterpret_cast<__nv_bfloat162*>(ph)     = __nv_bfloat162(h[0], h[1]);
            *reinterpret_cast<__nv_bfloat162*>(ph + 2) = __nv_bfloat162(h[2], h[3]);
            *reinterpret_cast<__nv_bfloat162*>(pl)     = __nv_bfloat162(l[0], l[1]);
            *reinterpret_cast<__nv_bfloat162*>(pl + 2) = __nv_bfloat162(l[2], l[3]);
        }
        __syncthreads();

        if (i < 3) {
            issueA(k0 + 32);
            issueB(k0 + 32, (i + 1) & 1);
            CPA_COMMIT();
        }

        const uint32_t uBh = sbase + OFF_BH0 + (i & 1) * BUFSZ;
        const uint32_t uBl = sbase + OFF_BL0 + (i & 1) * BUFSZ;

#pragma unroll
        for (int ks = 0; ks < 2; ks++) {
            uint32_t ah[2][4], al[2][4];
#pragma unroll
            for (int mt = 0; mt < 2; mt++) {
                int row = wm + mt * 16 + (lane & 15);
                int koff = ks * 16 + ((lane >> 4) << 3);
                uint32_t off = (uint32_t)(row * PITCH + koff) * 2;
                ldsm4(ah[mt], uAh + off);
                ldsm4(al[mt], uAl + off);
            }
#pragma unroll
            for (int np = 0; np < 4; np++) {
                int mat = lane >> 3;
                int row = wn + np * 16 + ((mat >> 1) << 3) + (lane & 7);
                int koff = ks * 16 + ((mat & 1) << 3);
                uint32_t off = (uint32_t)(row * PITCH + koff) * 2;
                uint32_t bh[4], bl[4];
                ldsm4(bh, uBh + off);
                ldsm4(bl, uBl + off);
#pragma unroll
                for (int mt = 0; mt < 2; mt++) {
                    mma_bf16(acc[mt][np * 2],     ah[mt], &bh[0]);
                    mma_bf16(acc[mt][np * 2],     ah[mt], &bl[0]);
                    mma_bf16(acc[mt][np * 2],     al[mt], &bh[0]);
                    mma_bf16(acc[mt][np * 2 + 1], ah[mt], &bh[2]);
                    mma_bf16(acc[mt][np * 2 + 1], ah[mt], &bl[2]);
                    mma_bf16(acc[mt][np * 2 + 1], al[mt], &bh[2]);
                }
            }
        }
        __syncthreads();
    }

    // epilogue: P1 (fp16), P3 (fp32), rtb (fp16); all ld = 128
    const int tr = lane >> 2;
    const int tc = (lane & 3) * 2;
    const bool toP3 = (m0 && bn == 128);
    __half* Ch = m0 ? d_P1h : d_rtbh;
#pragma unroll
    for (int mt = 0; mt < 2; mt++) {
        int grow0 = bm + wm + mt * 16 + tr;
        int grow1 = grow0 + 8;
#pragma unroll
        for (int nt = 0; nt < 8; nt++) {
            int lcol = wn + nt * 8 + tc;
            if (toP3) {
                if (grow0 < M)
                    *reinterpret_cast<float2*>(&d_P3[(size_t)grow0 * DIM + lcol]) =
                        make_float2(acc[mt][nt][0], acc[mt][nt][1]);
                if (grow1 < M)
                    *reinterpret_cast<float2*>(&d_P3[(size_t)grow1 * DIM + lcol]) =
                        make_float2(acc[mt][nt][2], acc[mt][nt][3]);
            } else {
                if (grow0 < M)
                    *reinterpret_cast<__half2*>(&Ch[(size_t)grow0 * DIM + lcol]) =
                        __floats2half2_rn(acc[mt][nt][0], acc[mt][nt][1]);
                if (grow1 < M)
                    *reinterpret_cast<__half2*>(&Ch[(size_t)grow1 * DIM + lcol]) =
                        __floats2half2_rn(acc[mt][nt][2], acc[mt][nt][3]);
            }
        }
    }
}

// ---------------- counting sort by dst -----------------------------
__global__ void k_count(const int* __restrict__ edges) {
    int e = blockIdx.x * blockDim.x + threadIdx.x;
    if (e >= NEDGES) return;
    int4 ed = reinterpret_cast<const int4*>(edges)[e];
    atomicAdd(&d_counts[ed.y], 1);
}

// ---- two-level scan: block sums -> scan sums -> final offsets ----
__global__ __launch_bounds__(256) void k_bsum() {
    int i = blockIdx.x * 256 + threadIdx.x;
    int lane = threadIdx.x & 31, w = threadIdx.x >> 5;
    int v = (i < NNODES) ? d_counts[i] : 0;
#pragma unroll
    for (int o = 16; o > 0; o >>= 1) v += __shfl_down_sync(0xFFFFFFFFu, v, o);
    __shared__ int ws[8];
    if (lane == 0) ws[w] = v;
    __syncthreads();
    if (threadIdx.x == 0) {
        int s = 0;
#pragma unroll
        for (int j = 0; j < 8; j++) s += ws[j];
        d_bsums[blockIdx.x] = s;
    }
}

__global__ __launch_bounds__(256) void k_scanb() {
    int t = threadIdx.x;
    int lane = t & 31, w = t >> 5;
    int v = (t < NBLK) ? d_bsums[t] : 0;
    int inc = v;
#pragma unroll
    for (int o = 1; o < 32; o <<= 1) {
        int u = __shfl_up_sync(0xFFFFFFFFu, inc, o);
        if (lane >= o) inc += u;
    }
    __shared__ int ws[8];
    if (lane == 31) ws[w] = inc;
    __syncthreads();
    if (w == 0 && lane < 8) {
        int s = ws[lane];
#pragma unroll
        for (int o = 1; o < 8; o <<= 1) {
            int u = __shfl_up_sync(0xFFu, s, o);
            if (lane >= o) s += u;
        }
        ws[lane] = s;
    }
    __syncthreads();
    int excl = inc - v + (w > 0 ? ws[w - 1] : 0);
    if (t < NBLK) d_bsums[t] = excl;
}

__global__ __launch_bounds__(256) void k_scanfin() {
    int b = blockIdx.x;
    int i = b * 256 + threadIdx.x;
    int lane = threadIdx.x & 31, w = threadIdx.x >> 5;
    int v = (i < NNODES) ? d_counts[i] : 0;
    int inc = v;
#pragma unroll
    for (int o = 1; o < 32; o <<= 1) {
        int u = __shfl_up_sync(0xFFFFFFFFu, inc, o);
        if (lane >= o) inc += u;
    }
    __shared__ int ws[8];
    if (lane == 31) ws[w] = inc;
    __syncthreads();
    if (w == 0 && lane < 8) {
        int s = ws[lane];
#pragma unroll
        for (int o = 1; o < 8; o <<= 1) {
            int u = __shfl_up_sync(0xFFu, s, o);
            if (lane >= o) s += u;
        }
        ws[lane] = s;
    }
    __syncthreads();
    int excl = inc - v + (w > 0 ? ws[w - 1] : 0) + d_bsums[b];
    if (i < NNODES) {
        d_offsets[i] = excl;
        d_cursor[i] = excl;
        if (i == NNODES - 1) d_offsets[NNODES] = excl + v;
    }
}

__global__ void k_scatter(const int* __restrict__ edges) {
    int e = blockIdx.x * blockDim.x + threadIdx.x;
    if (e >= NEDGES) return;
    int4 ed = reinterpret_cast<const int4*>(edges)[e];
    int pos = atomicAdd(&d_cursor[ed.y], 1);
    d_ssrc[pos] = ed.x;
    d_spair[pos] = ed.z * NTS + ed.w;
}

// ---------------- aggregation: warp per node, fp16 gathers, x4 ----
__device__ __forceinline__ void agg_accum(uint2 a, uint2 r, const float4& c3,
                                          float& ax, float& ay, float& az, float& aw) {
    float2 alo = __half22float2(*reinterpret_cast<const __half2*>(&a.x));
    float2 ahi = __half22float2(*reinterpret_cast<const __half2*>(&a.y));
    float2 rlo = __half22float2(*reinterpret_cast<const __half2*>(&r.x));
    float2 rhi = __half22float2(*reinterpret_cast<const __half2*>(&r.y));
    ax += lrelu(alo.x + rlo.x + c3.x);
    ay += lrelu(alo.y + rlo.y + c3.y);
    az += lrelu(ahi.x + rhi.x + c3.z);
    aw += lrelu(ahi.y + rhi.y + c3.w);
}

__global__ __launch_bounds__(256) void k_agg(float* __restrict__ out,
                                             const float* __restrict__ b_fc) {
    int warp = (blockIdx.x * blockDim.x + threadIdx.x) >> 5;
    int lane = threadIdx.x & 31;
    if (warp >= NNODES) return;

    int s0 = d_offsets[warp];
    int s1 = d_offsets[warp + 1];

    const uint2* P1 = reinterpret_cast<const uint2*>(d_P1h);
    const uint2* R  = reinterpret_cast<const uint2*>(d_rtbh);
    const float4* P3 = reinterpret_cast<const float4*>(d_P3);

    float4 bias4 = reinterpret_cast<const float4*>(b_fc)[lane];
    float4 c3 = P3[warp * 32 + lane];
    c3.x += bias4.x; c3.y += bias4.y; c3.z += bias4.z; c3.w += bias4.w;

    float ax = 0.f, ay = 0.f, az = 0.f, aw = 0.f;
    int i = s0;
    for (; i + 4 <= s1; i += 4) {
        int sA = __ldg(&d_ssrc[i]);
        int sB = __ldg(&d_ssrc[i + 1]);
        int sC = __ldg(&d_ssrc[i + 2]);
        int sD = __ldg(&d_ssrc[i + 3]);
        int pA = __ldg(&d_spair[i]);
        int pB = __ldg(&d_spair[i + 1]);
        int pC = __ldg(&d_spair[i + 2]);
        int pD = __ldg(&d_spair[i + 3]);
        uint2 a0 = __ldg(&P1[sA * 32 + lane]);
        uint2 r0 = __ldg(&R[pA * 32 + lane]);
        uint2 a1 = __ldg(&P1[sB * 32 + lane]);
        uint2 r1 = __ldg(&R[pB * 32 + lane]);
        uint2 a2 = __ldg(&P1[sC * 32 + lane]);
        uint2 r2 = __ldg(&R[pC * 32 + lane]);
        uint2 a3 = __ldg(&P1[sD * 32 + lane]);
        uint2 r3 = __ldg(&R[pD * 32 + lane]);
        agg_accum(a0, r0, c3, ax, ay, az, aw);
        agg_accum(a1, r1, c3, ax, ay, az, aw);
        agg_accum(a2, r2, c3, ax, ay, az, aw);
        agg_accum(a3, r3, c3, ax, ay, az, aw);
    }
    for (; i < s1; i++) {
        int s = __ldg(&d_ssrc[i]);
        int pr = __ldg(&d_spair[i]);
        uint2 a0 = __ldg(&P1[s * 32 + lane]);
        uint2 r0 = __ldg(&R[pr * 32 + lane]);
        agg_accum(a0, r0, c3, ax, ay, az, aw);
    }
    int cnt = s1 - s0;
    float inv = 1.0f / (float)(cnt > 0 ? cnt : 1);
    float4 r;
    r.x = ax * inv; r.y = ay * inv; r.z = az * inv; r.w = aw * inv;
    reinterpret_cast<float4*>(out)[warp * 32 + lane] = r;
}

// ---------------- launcher ----------------------------------------
extern "C" void kernel_launch(void* const* d_in, const int* in_sizes, int n_in,
                              void* d_out, int out_size) {
    const float* x          = (const float*)d_in[0];
    const float* rel_table  = (const float*)d_in[1];
    const float* time_table = (const float*)d_in[2];
    const float* W_rt       = (const float*)d_in[3];
    const float* b_rt       = (const float*)d_in[4];
    const float* W_fc       = (const float*)d_in[5];
    const float* b_fc       = (const float*)d_in[6];
    const int*   edges      = (const int*)d_in[7];
    float* out = (float*)d_out;

    cudaFuncSetAttribute(hmma_all, cudaFuncAttributeMaxDynamicSharedMemorySize, SM_TOTAL);

    // side stream + fork/join events (created once, before first capture)
    static cudaStream_t s1 = nullptr;
    static cudaEvent_t evFork = nullptr, evJoin = nullptr;
    if (!s1) {
        cudaStreamCreateWithFlags(&s1, cudaStreamNonBlocking);
        cudaEventCreateWithFlags(&evFork, cudaEventDisableTiming);
        cudaEventCreateWithFlags(&evJoin, cudaEventDisableTiming);
    }

    void* pCounts;
    cudaGetSymbolAddress(&pCounts, d_counts);

    // ---- fork: sort chain on side stream, GEMM chain on main ----
    cudaEventRecord(evFork, 0);
    cudaStreamWaitEvent(s1, evFork, 0);

    cudaMemsetAsync(pCounts, 0, NNODES * sizeof(int), s1);
    k_count<<<(NEDGES + 255) / 256, 256, 0, s1>>>(edges);
    k_bsum<<<NBLK, 256, 0, s1>>>();
    k_scanb<<<1, 256, 0, s1>>>();
    k_scanfin<<<NBLK, 256, 0, s1>>>();
    k_scatter<<<(NEDGES + 255) / 256, 256, 0, s1>>>(edges);
    cudaEventRecord(evJoin, s1);

    // main stream: prep + both GEMMs
    k_prep<<<NREL + NTS + 192, 256>>>(rel_table, time_table, W_rt, W_fc);
    hmma_all<<<NB0 + NB1, 256, SM_TOTAL>>>(x, b_rt);

    // ---- join: aggregation needs both chains ----
    cudaStreamWaitEvent(0, evJoin, 0);
    k_agg<<<(NNODES * 32 + 255) / 256, 256>>>(out, b_fc);
}

// round 16
// speedup vs baseline: 1.0881x; 1.0063x over previous
#include <cuda_runtime.h>
#include <cuda_bf16.h>
#include <cuda_fp16.h>
#include <cstdint>

// ---------------- problem constants (fixed shapes) ----------------
#define NNODES 50000
#define NEDGES 400000
#define HID    64
#define NREL   230
#define NTS    365
#define NPAIR  (NREL * NTS)      // 83950
#define DIM    128               // 2*HID
#define SLOPE  0.2f

#define NB0 782                  // 2 * ceil(50000/128) mode-0 CTAs
#define NB1 657                  // ceil(83950/128)     mode-1 CTAs
#define NBLK ((NNODES + 255) / 256)   // 196 scan blocks

// ---------------- device scratch (static; no runtime alloc) -------
__device__ __align__(16) float d_relpart[NREL * DIM];
__device__ __align__(16) float d_timepart[NTS * DIM];
__device__ __align__(16) __half d_P1h[NNODES * DIM];      // x@W1 (fp16, gathered per edge)
__device__ __align__(16) float  d_P3[NNODES * DIM];       // x@W3 (fp32, once per node)
__device__ __align__(16) __half d_rtbh[NPAIR * DIM];      // V@W2 (fp16, gathered per edge)
__device__ __align__(16) __nv_bfloat16 d_bT_hi[2 * DIM * DIM];   // [W1|W3]^T : [256][128]
__device__ __align__(16) __nv_bfloat16 d_bT_lo[2 * DIM * DIM];
__device__ __align__(16) __nv_bfloat16 d_w2T_hi[DIM * DIM];      // W2^T : [128][128]
__device__ __align__(16) __nv_bfloat16 d_w2T_lo[DIM * DIM];
__device__ int d_counts[NNODES];
__device__ int d_bsums[NBLK];
__device__ int d_offsets[NNODES + 1];
__device__ int d_cursor[NNODES];
__device__ int d_ssrc[NEDGES];
__device__ int d_spair[NEDGES];

__device__ __forceinline__ float lrelu(float v) {
    return v >= 0.0f ? v : SLOPE * v;
}

__device__ __forceinline__ uint32_t smem_u32(const void* p) {
    uint32_t a;
    asm("{ .reg .u64 t; cvta.to.shared.u64 t, %1; cvt.u32.u64 %0, t; }"
        : "=r"(a) : "l"(p));
    return a;
}

__device__ __forceinline__ void ldsm4(uint32_t* r, uint32_t addr) {
    asm volatile("ldmatrix.sync.aligned.m8n8.x4.shared.b16 {%0,%1,%2,%3}, [%4];"
                 : "=r"(r[0]), "=r"(r[1]), "=r"(r[2]), "=r"(r[3]) : "r"(addr));
}

__device__ __forceinline__ void mma_bf16(float* d, const uint32_t* a, const uint32_t* b) {
    asm volatile(
        "mma.sync.aligned.m16n8k16.row.col.f32.bf16.bf16.f32 "
        "{%0,%1,%2,%3}, {%4,%5,%6,%7}, {%8,%9}, {%0,%1,%2,%3};"
        : "+f"(d[0]), "+f"(d[1]), "+f"(d[2]), "+f"(d[3])
        : "r"(a[0]), "r"(a[1]), "r"(a[2]), "r"(a[3]), "r"(b[0]), "r"(b[1]));
}

__device__ __forceinline__ void cpa16(uint32_t dst, const void* src, int srcsize) {
    asm volatile("cp.async.cg.shared.global [%0], [%1], 16, %2;"
                 :: "r"(dst), "l"(src), "r"(srcsize));
}
#define CPA_COMMIT() asm volatile("cp.async.commit_group;" ::: "memory")
#define CPA_WAIT0()  asm volatile("cp.async.wait_group 0;" ::: "memory")
#define CPA_WAIT1()  asm volatile("cp.async.wait_group 1;" ::: "memory")

// ---------------- split helpers ------------------------------------
__device__ __forceinline__ void bf16_split(float v, __nv_bfloat16& hi, __nv_bfloat16& lo) {
    hi = __float2bfloat16_rn(v);
    lo = __float2bfloat16_rn(v - __bfloat162float(hi));
}

// ---------------- merged prep: proj + weight transpose/split ------
__global__ void k_prep(const float* __restrict__ rel_table,
                       const float* __restrict__ time_table,
                       const float* __restrict__ W_rt,
                       const float* __restrict__ W_fc) {
    int b = blockIdx.x;
    int tid = threadIdx.x;
    if (b < NREL + NTS) {
        if (tid >= DIM) return;
        int j = tid;
        float acc = 0.0f;
        if (b < NREL) {
            const float* a = rel_table + b * HID;
#pragma unroll
            for (int k = 0; k < HID; k++) acc += a[k] * W_rt[k * DIM + j];
            d_relpart[b * DIM + j] = acc;
        } else {
            int r = b - NREL;
            const float* a = time_table + r * HID;
#pragma unroll
            for (int k = 0; k < HID; k++) acc += a[k] * W_rt[(HID + k) * DIM + j];
            d_timepart[r * DIM + j] = acc;
        }
    } else {
        int idx = (b - (NREL + NTS)) * 256 + tid;
        if (idx < 2 * DIM * DIM) {
            int n = idx >> 7, k = idx & 127;
            float v = (n < DIM) ? W_fc[k * DIM + n]
                                : W_fc[(2 * DIM + k) * DIM + (n - DIM)];
            __nv_bfloat16 h, l; bf16_split(v, h, l);
            d_bT_hi[idx] = h; d_bT_lo[idx] = l;
        } else if (idx < 3 * DIM * DIM) {
            int j = idx - 2 * DIM * DIM;
            int n = j >> 7, k = j & 127;
            float v = W_fc[(DIM + k) * DIM + n];
            __nv_bfloat16 h, l; bf16_split(v, h, l);
            d_w2T_hi[j] = h; d_w2T_lo[j] = l;
        }
    }
}

// ------- merged HMMA bf16x3 GEMM, depth-2 cp.async pipeline -------
#define PITCH 40   // halves per smem row (80B): conflict-free ldmatrix, 16B-aligned

// dynamic smem layout (bytes):
//   Ah 0..10240, Al 10240..20480                       (single pair)
//   B buf b (b=0..2): Bh at 20480+b*20480, Bl +10240   (triple buffer)
//   ARAW buf b (b=0,1): 81920 + b*16384                (double buffer)
#define OFF_AH      0
#define OFF_AL      10240
#define OFF_B(b)    (20480 + (b) * 20480)
#define OFF_ARAW(b) (81920 + (b) * 16384)
#define SM_TOTAL    114688

__global__ __launch_bounds__(256, 2) void hmma_all(
    const float* __restrict__ x,
    const float* __restrict__ b_rt)
{
    extern __shared__ char smem[];
    const uint32_t sbase = smem_u32(smem);
    const uint32_t uAh = sbase + OFF_AH;
    const uint32_t uAl = sbase + OFF_AL;

    const int tid = threadIdx.x;
    const int wid = tid >> 5;
    const int lane = tid & 31;
    const int bid = blockIdx.x;

    const bool m0 = (bid < NB0);
    int bm, bn, M;
    const __nv_bfloat16 *Bh_, *Bl_;
    if (m0) {
        bm = (bid >> 1) * 128; bn = (bid & 1) * 128;
        Bh_ = d_bT_hi; Bl_ = d_bT_lo; M = NNODES;
    } else {
        int b2 = bid - NB0;
        bm = b2 * 128; bn = 0;
        Bh_ = d_w2T_hi; Bl_ = d_w2T_lo; M = NPAIR;
    }

    const int wm = (wid & 3) * 32;
    const int wn = (wid >> 2) * 64;

    float acc[2][8][4];
#pragma unroll
    for (int i = 0; i < 2; i++)
#pragma unroll
        for (int j = 0; j < 8; j++)
#pragma unroll
            for (int k = 0; k < 4; k++) acc[i][j][k] = 0.0f;

    const int a_c = (tid & 7) * 4;        // convert: float4 col within 32-chunk
    const int a_r0 = tid >> 3;            // rows a_r0 + 32*j
    const int b_c = (tid & 3) * 8;        // B cp.async: 8 halves (16B)
    const int b_r0 = tid >> 2;            // rows b_r0 + 64*j

    // issue group for chunk c: B hi/lo into buf c%3 (+ A raw into buf c&1, mode0)
    auto issueB = [&](int c) {
        const int k0 = c * 32;
        uint32_t dBh = sbase + OFF_B(c % 3);
        uint32_t dBl = dBh + 10240;
#pragma unroll
        for (int j = 0; j < 2; j++) {
            int row = b_r0 + j * 64;
            uint32_t so = (uint32_t)(row * PITCH + b_c) * 2;
            cpa16(dBh + so, Bh_ + (bn + row) * DIM + k0 + b_c, 16);
            cpa16(dBl + so, Bl_ + (bn + row) * DIM + k0 + b_c, 16);
        }
    };
    auto issueA = [&](int c) {
        if (!m0) return;
        const int k0 = c * 32;
        const uint32_t dA = sbase + OFF_ARAW(c & 1);
#pragma unroll
        for (int j = 0; j < 4; j++) {
            int u = tid + 256 * j;
            int row = u >> 3;
            int cg = (u & 7) * 4;
            int grow = bm + row;
            int ok = (grow < M) ? 16 : 0;
            int gr = (grow < M) ? grow : (M - 1);
            cpa16(dA + (uint32_t)(row * 32 + cg) * 4,
                  x + (size_t)gr * DIM + k0 + cg, ok);
        }
    };

    // convert chunk c: ARAW(c&1) (mode0) or tables (mode1) -> Ah/Al
    auto convert = [&](int c) {
        const int k0 = c * 32;
#pragma unroll
        for (int j = 0; j < 4; j++) {
            int row = a_r0 + j * 32;
            float4 v;
            if (m0) {
                v = *reinterpret_cast<const float4*>(
                        smem + OFF_ARAW(c & 1) + (size_t)(row * 32 + a_c) * 4);
            } else {
                int grow = bm + row;
                v = make_float4(0.f, 0.f, 0.f, 0.f);
                if (grow < M) {
                    int r = grow / NTS;
                    int t = grow - r * NTS;
                    float4 rv = *reinterpret_cast<const float4*>(&d_relpart[r * DIM + k0 + a_c]);
                    float4 tv = *reinterpret_cast<const float4*>(&d_timepart[t * DIM + k0 + a_c]);
                    float4 bv = *reinterpret_cast<const float4*>(&b_rt[k0 + a_c]);
                    v.x = lrelu(rv.x + tv.x + bv.x);
                    v.y = lrelu(rv.y + tv.y + bv.y);
                    v.z = lrelu(rv.z + tv.z + bv.z);
                    v.w = lrelu(rv.w + tv.w + bv.w);
                }
            }
            __nv_bfloat16 h[4], l[4];
            bf16_split(v.x, h[0], l[0]); bf16_split(v.y, h[1], l[1]);
            bf16_split(v.z, h[2], l[2]); bf16_split(v.w, h[3], l[3]);
            __nv_bfloat16* ph = reinterpret_cast<__nv_bfloat16*>(smem + OFF_AH) + row * PITCH + a_c;
            __nv_bfloat16* pl = reinterpret_cast<__nv_bfloat16*>(smem + OFF_AL) + row * PITCH + a_c;
            *reinterpret_cast<__nv_bfloat162*>(ph)     = __nv_bfloat162(h[0], h[1]);
            *reinterpret_cast<__nv_bfloat162*>(ph + 2) = __nv_bfloat162(h[2], h[3]);
            *reinterpret_cast<__nv_bfloat162*>(pl)     = __nv_bfloat162(l[0], l[1]);
            *reinterpret_cast<__nv_bfloat162*>(pl + 2) = __nv_bfloat162(l[2], l[3]);
        }
    };

    // prologue: chunks 0 and 1 in flight (two groups)
    issueA(0); issueB(0); CPA_COMMIT();
    issueA(1); issueB(1); CPA_COMMIT();

    for (int i = 0; i < 4; i++) {
        if (i < 3) { CPA_WAIT1(); } else { CPA_WAIT0(); }   // group i complete
        __syncthreads();          // data visible; Ah/Al free of prev MMA readers

        convert(i);
        __syncthreads();          // Ah/Al visible

        if (i < 2) { issueA(i + 2); issueB(i + 2); CPA_COMMIT(); }

        const uint32_t uBh = sbase + OFF_B(i % 3);
        const uint32_t uBl = uBh + 10240;
#pragma unroll
        for (int ks = 0; ks < 2; ks++) {
            uint32_t ah[2][4], al[2][4];
#pragma unroll
            for (int mt = 0; mt < 2; mt++) {
                int row = wm + mt * 16 + (lane & 15);
                int koff = ks * 16 + ((lane >> 4) << 3);
                uint32_t off = (uint32_t)(row * PITCH + koff) * 2;
                ldsm4(ah[mt], uAh + off);
                ldsm4(al[mt], uAl + off);
            }
#pragma unroll
            for (int np = 0; np < 4; np++) {
                int mat = lane >> 3;
                int row = wn + np * 16 + ((mat >> 1) << 3) + (lane & 7);
                int koff = ks * 16 + ((mat & 1) << 3);
                uint32_t off = (uint32_t)(row * PITCH + koff) * 2;
                uint32_t bh[4], bl[4];
                ldsm4(bh, uBh + off);
                ldsm4(bl, uBl + off);
#pragma unroll
                for (int mt = 0; mt < 2; mt++) {
                    mma_bf16(acc[mt][np * 2],     ah[mt], &bh[0]);
                    mma_bf16(acc[mt][np * 2],     ah[mt], &bl[0]);
                    mma_bf16(acc[mt][np * 2],     al[mt], &bh[0]);
                    mma_bf16(acc[mt][np * 2 + 1], ah[mt], &bh[2]);
                    mma_bf16(acc[mt][np * 2 + 1], ah[mt], &bl[2]);
                    mma_bf16(acc[mt][np * 2 + 1], al[mt], &bh[2]);
                }
            }
        }
    }

    // epilogue: P1 (fp16), P3 (fp32), rtb (fp16); all ld = 128
    const int tr = lane >> 2;
    const int tc = (lane & 3) * 2;
    const bool toP3 = (m0 && bn == 128);
    __half* Ch = m0 ? d_P1h : d_rtbh;
#pragma unroll
    for (int mt = 0; mt < 2; mt++) {
        int grow0 = bm + wm + mt * 16 + tr;
        int grow1 = grow0 + 8;
#pragma unroll
        for (int nt = 0; nt < 8; nt++) {
            int lcol = wn + nt * 8 + tc;
            if (toP3) {
                if (grow0 < M)
                    *reinterpret_cast<float2*>(&d_P3[(size_t)grow0 * DIM + lcol]) =
                        make_float2(acc[mt][nt][0], acc[mt][nt][1]);
                if (grow1 < M)
                    *reinterpret_cast<float2*>(&d_P3[(size_t)grow1 * DIM + lcol]) =
                        make_float2(acc[mt][nt][2], acc[mt][nt][3]);
            } else {
                if (grow0 < M)
                    *reinterpret_cast<__half2*>(&Ch[(size_t)grow0 * DIM + lcol]) =
                        __floats2half2_rn(acc[mt][nt][0], acc[mt][nt][1]);
                if (grow1 < M)
                    *reinterpret_cast<__half2*>(&Ch[(size_t)grow1 * DIM + lcol]) =
                        __floats2half2_rn(acc[mt][nt][2], acc[mt][nt][3]);
            }
        }
    }
}

// ---------------- counting sort by dst -----------------------------
__global__ void k_count(const int* __restrict__ edges) {
    int e = blockIdx.x * blockDim.x + threadIdx.x;
    if (e >= NEDGES) return;
    int4 ed = reinterpret_cast<const int4*>(edges)[e];
    atomicAdd(&d_counts[ed.y], 1);
}

// ---- two-level scan: block sums -> scan sums -> final offsets ----
__global__ __launch_bounds__(256) void k_bsum() {
    int i = blockIdx.x * 256 + threadIdx.x;
    int lane = threadIdx.x & 31, w = threadIdx.x >> 5;
    int v = (i < NNODES) ? d_counts[i] : 0;
#pragma unroll
    for (int o = 16; o > 0; o >>= 1) v += __shfl_down_sync(0xFFFFFFFFu, v, o);
    __shared__ int ws[8];
    if (lane == 0) ws[w] = v;
    __syncthreads();
    if (threadIdx.x == 0) {
        int s = 0;
#pragma unroll
        for (int j = 0; j < 8; j++) s += ws[j];
        d_bsums[blockIdx.x] = s;
    }
}

__global__ __launch_bounds__(256) void k_scanb() {
    int t = threadIdx.x;
    int lane = t & 31, w = t >> 5;
    int v = (t < NBLK) ? d_bsums[t] : 0;
    int inc = v;
#pragma unroll
    for (int o = 1; o < 32; o <<= 1) {
        int u = __shfl_up_sync(0xFFFFFFFFu, inc, o);
        if (lane >= o) inc += u;
    }
    __shared__ int ws[8];
    if (lane == 31) ws[w] = inc;
    __syncthreads();
    if (w == 0 && lane < 8) {
        int s = ws[lane];
#pragma unroll
        for (int o = 1; o < 8; o <<= 1) {
            int u = __shfl_up_sync(0xFFu, s, o);
            if (lane >= o) s += u;
        }
        ws[lane] = s;
    }
    __syncthreads();
    int excl = inc - v + (w > 0 ? ws[w - 1] : 0);
    if (t < NBLK) d_bsums[t] = excl;
}

__global__ __launch_bounds__(256) void k_scanfin() {
    int b = blockIdx.x;
    int i = b * 256 + threadIdx.x;
    int lane = threadIdx.x & 31, w = threadIdx.x >> 5;
    int v = (i < NNODES) ? d_counts[i] : 0;
    int inc = v;
#pragma unroll
    for (int o = 1; o < 32; o <<= 1) {
        int u = __shfl_up_sync(0xFFFFFFFFu, inc, o);
        if (lane >= o) inc += u;
    }
    __shared__ int ws[8];
    if (lane == 31) ws[w] = inc;
    __syncthreads();
    if (w == 0 && lane < 8) {
        int s = ws[lane];
#pragma unroll
        for (int o = 1; o < 8; o <<= 1) {
            int u = __shfl_up_sync(0xFFu, s, o);
            if (lane >= o) s += u;
        }
        ws[lane] = s;
    }
    __syncthreads();
    int excl = inc - v + (w > 0 ? ws[w - 1] : 0) + d_bsums[b];
    if (i < NNODES) {
        d_offsets[i] = excl;
        d_cursor[i] = excl;
        if (i == NNODES - 1) d_offsets[NNODES] = excl + v;
    }
}

__global__ void k_scatter(const int* __restrict__ edges) {
    int e = blockIdx.x * blockDim.x + threadIdx.x;
    if (e >= NEDGES) return;
    int4 ed = reinterpret_cast<const int4*>(edges)[e];
    int pos = atomicAdd(&d_cursor[ed.y], 1);
    d_ssrc[pos] = ed.x;
    d_spair[pos] = ed.z * NTS + ed.w;
}

// ---------------- aggregation: warp per node, fp16 gathers, x4 ----
__device__ __forceinline__ void agg_accum(uint2 a, uint2 r, const float4& c3,
                                          float& ax, float& ay, float& az, float& aw) {
    float2 alo = __half22float2(*reinterpret_cast<const __half2*>(&a.x));
    float2 ahi = __half22float2(*reinterpret_cast<const __half2*>(&a.y));
    float2 rlo = __half22float2(*reinterpret_cast<const __half2*>(&r.x));
    float2 rhi = __half22float2(*reinterpret_cast<const __half2*>(&r.y));
    ax += lrelu(alo.x + rlo.x + c3.x);
    ay += lrelu(alo.y + rlo.y + c3.y);
    az += lrelu(ahi.x + rhi.x + c3.z);
    aw += lrelu(ahi.y + rhi.y + c3.w);
}

__global__ __launch_bounds__(256) void k_agg(float* __restrict__ out,
                                             const float* __restrict__ b_fc) {
    int warp = (blockIdx.x * blockDim.x + threadIdx.x) >> 5;
    int lane = threadIdx.x & 31;
    if (warp >= NNODES) return;

    int s0 = d_offsets[warp];
    int s1 = d_offsets[warp + 1];

    const uint2* P1 = reinterpret_cast<const uint2*>(d_P1h);
    const uint2* R  = reinterpret_cast<const uint2*>(d_rtbh);
    const float4* P3 = reinterpret_cast<const float4*>(d_P3);

    float4 bias4 = reinterpret_cast<const float4*>(b_fc)[lane];
    float4 c3 = P3[warp * 32 + lane];
    c3.x += bias4.x; c3.y += bias4.y; c3.z += bias4.z; c3.w += bias4.w;

    float ax = 0.f, ay = 0.f, az = 0.f, aw = 0.f;
    int i = s0;
    for (; i + 4 <= s1; i += 4) {
        int sA = __ldg(&d_ssrc[i]);
        int sB = __ldg(&d_ssrc[i + 1]);
        int sC = __ldg(&d_ssrc[i + 2]);
        int sD = __ldg(&d_ssrc[i + 3]);
        int pA = __ldg(&d_spair[i]);
        int pB = __ldg(&d_spair[i + 1]);
        int pC = __ldg(&d_spair[i + 2]);
        int pD = __ldg(&d_spair[i + 3]);
        uint2 a0 = __ldg(&P1[sA * 32 + lane]);
        uint2 r0 = __ldg(&R[pA * 32 + lane]);
        uint2 a1 = __ldg(&P1[sB * 32 + lane]);
        uint2 r1 = __ldg(&R[pB * 32 + lane]);
        uint2 a2 = __ldg(&P1[sC * 32 + lane]);
        uint2 r2 = __ldg(&R[pC * 32 + lane]);
        uint2 a3 = __ldg(&P1[sD * 32 + lane]);
        uint2 r3 = __ldg(&R[pD * 32 + lane]);
        agg_accum(a0, r0, c3, ax, ay, az, aw);
        agg_accum(a1, r1, c3, ax, ay, az, aw);
        agg_accum(a2, r2, c3, ax, ay, az, aw);
        agg_accum(a3, r3, c3, ax, ay, az, aw);
    }
    for (; i < s1; i++) {
        int s = __ldg(&d_ssrc[i]);
        int pr = __ldg(&d_spair[i]);
        uint2 a0 = __ldg(&P1[s * 32 + lane]);
        uint2 r0 = __ldg(&R[pr * 32 + lane]);
        agg_accum(a0, r0, c3, ax, ay, az, aw);
    }
    int cnt = s1 - s0;
    float inv = 1.0f / (float)(cnt > 0 ? cnt : 1);
    float4 r;
    r.x = ax * inv; r.y = ay * inv; r.z = az * inv; r.w = aw * inv;
    reinterpret_cast<float4*>(out)[warp * 32 + lane] = r;
}

// ---------------- launcher ----------------------------------------
extern "C" void kernel_launch(void* const* d_in, const int* in_sizes, int n_in,
                              void* d_out, int out_size) {
    const float* x          = (const float*)d_in[0];
    const float* rel_table  = (const float*)d_in[1];
    const float* time_table = (const float*)d_in[2];
    const float* W_rt       = (const float*)d_in[3];
    const float* b_rt       = (const float*)d_in[4];
    const float* W_fc       = (const float*)d_in[5];
    const float* b_fc       = (const float*)d_in[6];
    const int*   edges      = (const int*)d_in[7];
    float* out = (float*)d_out;

    cudaFuncSetAttribute(hmma_all, cudaFuncAttributeMaxDynamicSharedMemorySize, SM_TOTAL);

    // side stream + fork/join events (created once, before first capture)
    static cudaStream_t s1 = nullptr;
    static cudaEvent_t evFork = nullptr, evJoin = nullptr;
    if (!s1) {
        cudaStreamCreateWithFlags(&s1, cudaStreamNonBlocking);
        cudaEventCreateWithFlags(&evFork, cudaEventDisableTiming);
        cudaEventCreateWithFlags(&evJoin, cudaEventDisableTiming);
    }

    void* pCounts;
    cudaGetSymbolAddress(&pCounts, d_counts);

    // ---- fork: sort chain on side stream, GEMM chain on main ----
    cudaEventRecord(evFork, 0);
    cudaStreamWaitEvent(s1, evFork, 0);

    cudaMemsetAsync(pCounts, 0, NNODES * sizeof(int), s1);
    k_count<<<(NEDGES + 255) / 256, 256, 0, s1>>>(edges);
    k_bsum<<<NBLK, 256, 0, s1>>>();
    k_scanb<<<1, 256, 0, s1>>>();
    k_scanfin<<<NBLK, 256, 0, s1>>>();
    k_scatter<<<(NEDGES + 255) / 256, 256, 0, s1>>>(edges);
    cudaEventRecord(evJoin, s1);

    // main stream: prep + both GEMMs (depth-2 pipelined)
    k_prep<<<NREL + NTS + 192, 256>>>(rel_table, time_table, W_rt, W_fc);
    hmma_all<<<NB0 + NB1, 256, SM_TOTAL>>>(x, b_rt);

    // ---- join: aggregation needs both chains ----
    cudaStreamWaitEvent(0, evJoin, 0);
    k_agg<<<(NNODES * 32 + 255) / 256, 256>>>(out, b_fc);
}

// round 17
// speedup vs baseline: 1.1143x; 1.0241x over previous
#include <cuda_runtime.h>
#include <cuda_bf16.h>
#include <cuda_fp16.h>
#include <cstdint>

// ---------------- problem constants (fixed shapes) ----------------
#define NNODES 50000
#define NEDGES 400000
#define HID    64
#define NREL   230
#define NTS    365
#define NPAIR  (NREL * NTS)      // 83950
#define DIM    128               // 2*HID
#define SLOPE  0.2f

#define NB0 782                  // 2 * ceil(50000/128) mode-0 CTAs
#define NB1 657                  // ceil(83950/128)     mode-1 CTAs
#define NBLK ((NNODES + 255) / 256)   // 196 scan blocks

// ---------------- device scratch (static; no runtime alloc) -------
__device__ __align__(16) float d_relpart[NREL * DIM];
__device__ __align__(16) float d_timepart[NTS * DIM];
__device__ __align__(16) __half d_P1h[NNODES * DIM];      // x@W1 (fp16, gathered per edge)
__device__ __align__(16) float  d_P3[NNODES * DIM];       // x@W3 (fp32, once per node)
__device__ __align__(16) __half d_rtbh[NPAIR * DIM];      // V@W2 (fp16, gathered per edge)
__device__ __align__(16) __nv_bfloat16 d_bT_hi[2 * DIM * DIM];   // [W1|W3]^T : [256][128]
__device__ __align__(16) __nv_bfloat16 d_bT_lo[2 * DIM * DIM];
__device__ __align__(16) __nv_bfloat16 d_w2T_hi[DIM * DIM];      // W2^T : [128][128]
__device__ __align__(16) __nv_bfloat16 d_w2T_lo[DIM * DIM];
__device__ int d_counts[NNODES];          // zero-initialized; re-zeroed by k_scanfin
__device__ int d_bsums[NBLK];
__device__ int d_offsets[NNODES + 1];
__device__ int d_cursor[NNODES];
__device__ __align__(8) int2 d_sedge[NEDGES];   // (src, pair) packed

__device__ __forceinline__ float lrelu(float v) {
    return v >= 0.0f ? v : SLOPE * v;
}

__device__ __forceinline__ uint32_t smem_u32(const void* p) {
    uint32_t a;
    asm("{ .reg .u64 t; cvta.to.shared.u64 t, %1; cvt.u32.u64 %0, t; }"
        : "=r"(a) : "l"(p));
    return a;
}

__device__ __forceinline__ void ldsm4(uint32_t* r, uint32_t addr) {
    asm volatile("ldmatrix.sync.aligned.m8n8.x4.shared.b16 {%0,%1,%2,%3}, [%4];"
                 : "=r"(r[0]), "=r"(r[1]), "=r"(r[2]), "=r"(r[3]) : "r"(addr));
}

__device__ __forceinline__ void mma_bf16(float* d, const uint32_t* a, const uint32_t* b) {
    asm volatile(
        "mma.sync.aligned.m16n8k16.row.col.f32.bf16.bf16.f32 "
        "{%0,%1,%2,%3}, {%4,%5,%6,%7}, {%8,%9}, {%0,%1,%2,%3};"
        : "+f"(d[0]), "+f"(d[1]), "+f"(d[2]), "+f"(d[3])
        : "r"(a[0]), "r"(a[1]), "r"(a[2]), "r"(a[3]), "r"(b[0]), "r"(b[1]));
}

__device__ __forceinline__ void cpa16(uint32_t dst, const void* src, int srcsize) {
    asm volatile("cp.async.cg.shared.global [%0], [%1], 16, %2;"
                 :: "r"(dst), "l"(src), "r"(srcsize));
}
#define CPA_COMMIT() asm volatile("cp.async.commit_group;" ::: "memory")
#define CPA_WAIT0()  asm volatile("cp.async.wait_group 0;" ::: "memory")
#define CPA_WAIT1()  asm volatile("cp.async.wait_group 1;" ::: "memory")

// ---------------- split helpers ------------------------------------
__device__ __forceinline__ void bf16_split(float v, __nv_bfloat16& hi, __nv_bfloat16& lo) {
    hi = __float2bfloat16_rn(v);
    lo = __float2bfloat16_rn(v - __bfloat162float(hi));
}

// ---------------- merged prep: proj + weight transpose/split ------
__global__ void k_prep(const float* __restrict__ rel_table,
                       const float* __restrict__ time_table,
                       const float* __restrict__ W_rt,
                       const float* __restrict__ W_fc) {
    int b = blockIdx.x;
    int tid = threadIdx.x;
    if (b < NREL + NTS) {
        if (tid >= DIM) return;
        int j = tid;
        float acc = 0.0f;
        if (b < NREL) {
            const float* a = rel_table + b * HID;
#pragma unroll
            for (int k = 0; k < HID; k++) acc += a[k] * W_rt[k * DIM + j];
            d_relpart[b * DIM + j] = acc;
        } else {
            int r = b - NREL;
            const float* a = time_table + r * HID;
#pragma unroll
            for (int k = 0; k < HID; k++) acc += a[k] * W_rt[(HID + k) * DIM + j];
            d_timepart[r * DIM + j] = acc;
        }
    } else {
        int idx = (b - (NREL + NTS)) * 256 + tid;
        if (idx < 2 * DIM * DIM) {
            int n = idx >> 7, k = idx & 127;
            float v = (n < DIM) ? W_fc[k * DIM + n]
                                : W_fc[(2 * DIM + k) * DIM + (n - DIM)];
            __nv_bfloat16 h, l; bf16_split(v, h, l);
            d_bT_hi[idx] = h; d_bT_lo[idx] = l;
        } else if (idx < 3 * DIM * DIM) {
            int j = idx - 2 * DIM * DIM;
            int n = j >> 7, k = j & 127;
            float v = W_fc[(DIM + k) * DIM + n];
            __nv_bfloat16 h, l; bf16_split(v, h, l);
            d_w2T_hi[j] = h; d_w2T_lo[j] = l;
        }
    }
}

// ------- merged HMMA bf16x3 GEMM, depth-2 cp.async pipeline -------
#define PITCH 40   // halves per smem row (80B): conflict-free ldmatrix, 16B-aligned

// dynamic smem layout (bytes):
//   Ah 0..10240, Al 10240..20480                       (single pair)
//   B buf b (b=0..2): Bh at 20480+b*20480, Bl +10240   (triple buffer)
//   ARAW buf b (b=0,1): 81920 + b*16384                (double buffer)
#define OFF_AH      0
#define OFF_AL      10240
#define OFF_B(b)    (20480 + (b) * 20480)
#define OFF_ARAW(b) (81920 + (b) * 16384)
#define SM_TOTAL    114688

__global__ __launch_bounds__(256, 2) void hmma_all(
    const float* __restrict__ x,
    const float* __restrict__ b_rt)
{
    extern __shared__ char smem[];
    const uint32_t sbase = smem_u32(smem);
    const uint32_t uAh = sbase + OFF_AH;
    const uint32_t uAl = sbase + OFF_AL;

    const int tid = threadIdx.x;
    const int wid = tid >> 5;
    const int lane = tid & 31;
    const int bid = blockIdx.x;

    const bool m0 = (bid < NB0);
    int bm, bn, M;
    const __nv_bfloat16 *Bh_, *Bl_;
    if (m0) {
        bm = (bid >> 1) * 128; bn = (bid & 1) * 128;
        Bh_ = d_bT_hi; Bl_ = d_bT_lo; M = NNODES;
    } else {
        int b2 = bid - NB0;
        bm = b2 * 128; bn = 0;
        Bh_ = d_w2T_hi; Bl_ = d_w2T_lo; M = NPAIR;
    }

    const int wm = (wid & 3) * 32;
    const int wn = (wid >> 2) * 64;

    float acc[2][8][4];
#pragma unroll
    for (int i = 0; i < 2; i++)
#pragma unroll
        for (int j = 0; j < 8; j++)
#pragma unroll
            for (int k = 0; k < 4; k++) acc[i][j][k] = 0.0f;

    const int a_c = (tid & 7) * 4;        // convert: float4 col within 32-chunk
    const int a_r0 = tid >> 3;            // rows a_r0 + 32*j
    const int b_c = (tid & 3) * 8;        // B cp.async: 8 halves (16B)
    const int b_r0 = tid >> 2;            // rows b_r0 + 64*j

    auto issueB = [&](int c) {
        const int k0 = c * 32;
        uint32_t dBh = sbase + OFF_B(c % 3);
        uint32_t dBl = dBh + 10240;
#pragma unroll
        for (int j = 0; j < 2; j++) {
            int row = b_r0 + j * 64;
            uint32_t so = (uint32_t)(row * PITCH + b_c) * 2;
            cpa16(dBh + so, Bh_ + (bn + row) * DIM + k0 + b_c, 16);
            cpa16(dBl + so, Bl_ + (bn + row) * DIM + k0 + b_c, 16);
        }
    };
    auto issueA = [&](int c) {
        if (!m0) return;
        const int k0 = c * 32;
        const uint32_t dA = sbase + OFF_ARAW(c & 1);
#pragma unroll
        for (int j = 0; j < 4; j++) {
            int u = tid + 256 * j;
            int row = u >> 3;
            int cg = (u & 7) * 4;
            int grow = bm + row;
            int ok = (grow < M) ? 16 : 0;
            int gr = (grow < M) ? grow : (M - 1);
            cpa16(dA + (uint32_t)(row * 32 + cg) * 4,
                  x + (size_t)gr * DIM + k0 + cg, ok);
        }
    };

    auto convert = [&](int c) {
        const int k0 = c * 32;
#pragma unroll
        for (int j = 0; j < 4; j++) {
            int row = a_r0 + j * 32;
            float4 v;
            if (m0) {
                v = *reinterpret_cast<const float4*>(
                        smem + OFF_ARAW(c & 1) + (size_t)(row * 32 + a_c) * 4);
            } else {
                int grow = bm + row;
                v = make_float4(0.f, 0.f, 0.f, 0.f);
                if (grow < M) {
                    int r = grow / NTS;
                    int t = grow - r * NTS;
                    float4 rv = *reinterpret_cast<const float4*>(&d_relpart[r * DIM + k0 + a_c]);
                    float4 tv = *reinterpret_cast<const float4*>(&d_timepart[t * DIM + k0 + a_c]);
                    float4 bv = *reinterpret_cast<const float4*>(&b_rt[k0 + a_c]);
                    v.x = lrelu(rv.x + tv.x + bv.x);
                    v.y = lrelu(rv.y + tv.y + bv.y);
                    v.z = lrelu(rv.z + tv.z + bv.z);
                    v.w = lrelu(rv.w + tv.w + bv.w);
                }
            }
            __nv_bfloat16 h[4], l[4];
            bf16_split(v.x, h[0], l[0]); bf16_split(v.y, h[1], l[1]);
            bf16_split(v.z, h[2], l[2]); bf16_split(v.w, h[3], l[3]);
            __nv_bfloat16* ph = reinterpret_cast<__nv_bfloat16*>(smem + OFF_AH) + row * PITCH + a_c;
            __nv_bfloat16* pl = reinterpret_cast<__nv_bfloat16*>(smem + OFF_AL) + row * PITCH + a_c;
            *reinterpret_cast<__nv_bfloat162*>(ph)     = __nv_bfloat162(h[0], h[1]);
            *reinterpret_cast<__nv_bfloat162*>(ph + 2) = __nv_bfloat162(h[2], h[3]);
            *reinterpret_cast<__nv_bfloat162*>(pl)     = __nv_bfloat162(l[0], l[1]);
            *reinterpret_cast<__nv_bfloat162*>(pl + 2) = __nv_bfloat162(l[2], l[3]);
        }
    };

    // prologue: chunks 0 and 1 in flight (two groups)
    issueA(0); issueB(0); CPA_COMMIT();
    issueA(1); issueB(1); CPA_COMMIT();

    for (int i = 0; i < 4; i++) {
        if (i < 3) { CPA_WAIT1(); } else { CPA_WAIT0(); }   // group i complete
        __syncthreads();          // data visible; Ah/Al free of prev MMA readers

        convert(i);
        __syncthreads();          // Ah/Al visible

        if (i < 2) { issueA(i + 2); issueB(i + 2); CPA_COMMIT(); }

        const uint32_t uBh = sbase + OFF_B(i % 3);
        const uint32_t uBl = uBh + 10240;
#pragma unroll
        for (int ks = 0; ks < 2; ks++) {
            uint32_t ah[2][4], al[2][4];
#pragma unroll
            for (int mt = 0; mt < 2; mt++) {
                int row = wm + mt * 16 + (lane & 15);
                int koff = ks * 16 + ((lane >> 4) << 3);
                uint32_t off = (uint32_t)(row * PITCH + koff) * 2;
                ldsm4(ah[mt], uAh + off);
                ldsm4(al[mt], uAl + off);
            }
#pragma unroll
            for (int np = 0; np < 4; np++) {
                int mat = lane >> 3;
                int row = wn + np * 16 + ((mat >> 1) << 3) + (lane & 7);
                int koff = ks * 16 + ((mat & 1) << 3);
                uint32_t off = (uint32_t)(row * PITCH + koff) * 2;
                uint32_t bh[4], bl[4];
                ldsm4(bh, uBh + off);
                ldsm4(bl, uBl + off);
#pragma unroll
                for (int mt = 0; mt < 2; mt++) {
                    mma_bf16(acc[mt][np * 2],     ah[mt], &bh[0]);
                    mma_bf16(acc[mt][np * 2],     ah[mt], &bl[0]);
                    mma_bf16(acc[mt][np * 2],     al[mt], &bh[0]);
                    mma_bf16(acc[mt][np * 2 + 1], ah[mt], &bh[2]);
                    mma_bf16(acc[mt][np * 2 + 1], ah[mt], &bl[2]);
                    mma_bf16(acc[mt][np * 2 + 1], al[mt], &bh[2]);
                }
            }
        }
    }

    // epilogue: P1 (fp16), P3 (fp32), rtb (fp16); all ld = 128
    const int tr = lane >> 2;
    const int tc = (lane & 3) * 2;
    const bool toP3 = (m0 && bn == 128);
    __half* Ch = m0 ? d_P1h : d_rtbh;
#pragma unroll
    for (int mt = 0; mt < 2; mt++) {
        int grow0 = bm + wm + mt * 16 + tr;
        int grow1 = grow0 + 8;
#pragma unroll
        for (int nt = 0; nt < 8; nt++) {
            int lcol = wn + nt * 8 + tc;
            if (toP3) {
                if (grow0 < M)
                    *reinterpret_cast<float2*>(&d_P3[(size_t)grow0 * DIM + lcol]) =
                        make_float2(acc[mt][nt][0], acc[mt][nt][1]);
                if (grow1 < M)
                    *reinterpret_cast<float2*>(&d_P3[(size_t)grow1 * DIM + lcol]) =
                        make_float2(acc[mt][nt][2], acc[mt][nt][3]);
            } else {
                if (grow0 < M)
                    *reinterpret_cast<__half2*>(&Ch[(size_t)grow0 * DIM + lcol]) =
                        __floats2half2_rn(acc[mt][nt][0], acc[mt][nt][1]);
                if (grow1 < M)
                    *reinterpret_cast<__half2*>(&Ch[(size_t)grow1 * DIM + lcol]) =
                        __floats2half2_rn(acc[mt][nt][2], acc[mt][nt][3]);
            }
        }
    }
}

// ---------------- counting sort by dst -----------------------------
__global__ void k_count(const int* __restrict__ edges) {
    int e = blockIdx.x * blockDim.x + threadIdx.x;
    if (e >= NEDGES) return;
    int4 ed = reinterpret_cast<const int4*>(edges)[e];
    atomicAdd(&d_counts[ed.y], 1);
}

// ---- two-level scan: block sums -> scan sums -> final offsets ----
__global__ __launch_bounds__(256) void k_bsum() {
    int i = blockIdx.x * 256 + threadIdx.x;
    int lane = threadIdx.x & 31, w = threadIdx.x >> 5;
    int v = (i < NNODES) ? d_counts[i] : 0;
#pragma unroll
    for (int o = 16; o > 0; o >>= 1) v += __shfl_down_sync(0xFFFFFFFFu, v, o);
    __shared__ int ws[8];
    if (lane == 0) ws[w] = v;
    __syncthreads();
    if (threadIdx.x == 0) {
        int s = 0;
#pragma unroll
        for (int j = 0; j < 8; j++) s += ws[j];
        d_bsums[blockIdx.x] = s;
    }
}

__global__ __launch_bounds__(256) void k_scanb() {
    int t = threadIdx.x;
    int lane = t & 31, w = t >> 5;
    int v = (t < NBLK) ? d_bsums[t] : 0;
    int inc = v;
#pragma unroll
    for (int o = 1; o < 32; o <<= 1) {
        int u = __shfl_up_sync(0xFFFFFFFFu, inc, o);
        if (lane >= o) inc += u;
    }
    __shared__ int ws[8];
    if (lane == 31) ws[w] = inc;
    __syncthreads();
    if (w == 0 && lane < 8) {
        int s = ws[lane];
#pragma unroll
        for (int o = 1; o < 8; o <<= 1) {
            int u = __shfl_up_sync(0xFFu, s, o);
            if (lane >= o) s += u;
        }
        ws[lane] = s;
    }
    __syncthreads();
    int excl = inc - v + (w > 0 ? ws[w - 1] : 0);
    if (t < NBLK) d_bsums[t] = excl;
}

__global__ __launch_bounds__(256) void k_scanfin() {
    int b = blockIdx.x;
    int i = b * 256 + threadIdx.x;
    int lane = threadIdx.x & 31, w = threadIdx.x >> 5;
    int v = (i < NNODES) ? d_counts[i] : 0;
    int inc = v;
#pragma unroll
    for (int o = 1; o < 32; o <<= 1) {
        int u = __shfl_up_sync(0xFFFFFFFFu, inc, o);
        if (lane >= o) inc += u;
    }
    __shared__ int ws[8];
    if (lane == 31) ws[w] = inc;
    __syncthreads();
    if (w == 0 && lane < 8) {
        int s = ws[lane];
#pragma unroll
        for (int o = 1; o < 8; o <<= 1) {
            int u = __shfl_up_sync(0xFFu, s, o);
            if (lane >= o) s += u;
        }
        ws[lane] = s;
    }
    __syncthreads();
    int excl = inc - v + (w > 0 ? ws[w - 1] : 0) + d_bsums[b];
    if (i < NNODES) {
        d_offsets[i] = excl;
        d_cursor[i] = excl;
        d_counts[i] = 0;                     // re-zero for next graph replay
        if (i == NNODES - 1) d_offsets[NNODES] = excl + v;
    }
}

__global__ void k_scatter(const int* __restrict__ edges) {
    int e = blockIdx.x * blockDim.x + threadIdx.x;
    if (e >= NEDGES) return;
    int4 ed = reinterpret_cast<const int4*>(edges)[e];
    int pos = atomicAdd(&d_cursor[ed.y], 1);
    d_sedge[pos] = make_int2(ed.x, ed.z * NTS + ed.w);
}

// ---------------- aggregation: warp per node, fp16 gathers, x4 ----
__device__ __forceinline__ void agg_accum(uint2 a, uint2 r, const float4& c3,
                                          float& ax, float& ay, float& az, float& aw) {
    float2 alo = __half22float2(*reinterpret_cast<const __half2*>(&a.x));
    float2 ahi = __half22float2(*reinterpret_cast<const __half2*>(&a.y));
    float2 rlo = __half22float2(*reinterpret_cast<const __half2*>(&r.x));
    float2 rhi = __half22float2(*reinterpret_cast<const __half2*>(&r.y));
    ax += lrelu(alo.x + rlo.x + c3.x);
    ay += lrelu(alo.y + rlo.y + c3.y);
    az += lrelu(ahi.x + rhi.x + c3.z);
    aw += lrelu(ahi.y + rhi.y + c3.w);
}

__global__ __launch_bounds__(256) void k_agg(float* __restrict__ out,
                                             const float* __restrict__ b_fc) {
    int warp = (blockIdx.x * blockDim.x + threadIdx.x) >> 5;
    int lane = threadIdx.x & 31;
    if (warp >= NNODES) return;

    int s0 = d_offsets[warp];
    int s1 = d_offsets[warp + 1];

    const uint2* P1 = reinterpret_cast<const uint2*>(d_P1h);
    const uint2* R  = reinterpret_cast<const uint2*>(d_rtbh);
    const float4* P3 = reinterpret_cast<const float4*>(d_P3);

    float4 bias4 = reinterpret_cast<const float4*>(b_fc)[lane];
    float4 c3 = P3[warp * 32 + lane];
    c3.x += bias4.x; c3.y += bias4.y; c3.z += bias4.z; c3.w += bias4.w;

    float ax = 0.f, ay = 0.f, az = 0.f, aw = 0.f;
    int i = s0;
    for (; i + 4 <= s1; i += 4) {
        int2 eA = __ldg(&d_sedge[i]);
        int2 eB = __ldg(&d_sedge[i + 1]);
        int2 eC = __ldg(&d_sedge[i + 2]);
        int2 eD = __ldg(&d_sedge[i + 3]);
        uint2 a0 = __ldg(&P1[eA.x * 32 + lane]);
        uint2 r0 = __ldg(&R[eA.y * 32 + lane]);
        uint2 a1 = __ldg(&P1[eB.x * 32 + lane]);
        uint2 r1 = __ldg(&R[eB.y * 32 + lane]);
        uint2 a2 = __ldg(&P1[eC.x * 32 + lane]);
        uint2 r2 = __ldg(&R[eC.y * 32 + lane]);
        uint2 a3 = __ldg(&P1[eD.x * 32 + lane]);
        uint2 r3 = __ldg(&R[eD.y * 32 + lane]);
        agg_accum(a0, r0, c3, ax, ay, az, aw);
        agg_accum(a1, r1, c3, ax, ay, az, aw);
        agg_accum(a2, r2, c3, ax, ay, az, aw);
        agg_accum(a3, r3, c3, ax, ay, az, aw);
    }
    for (; i < s1; i++) {
        int2 e = __ldg(&d_sedge[i]);
        uint2 a0 = __ldg(&P1[e.x * 32 + lane]);
        uint2 r0 = __ldg(&R[e.y * 32 + lane]);
        agg_accum(a0, r0, c3, ax, ay, az, aw);
    }
    int cnt = s1 - s0;
    float inv = 1.0f / (float)(cnt > 0 ? cnt : 1);
    float4 r;
    r.x = ax * inv; r.y = ay * inv; r.z = az * inv; r.w = aw * inv;
    reinterpret_cast<float4*>(out)[warp * 32 + lane] = r;
}

// ---------------- launcher ----------------------------------------
extern "C" void kernel_launch(void* const* d_in, const int* in_sizes, int n_in,
                              void* d_out, int out_size) {
    const float* x          = (const float*)d_in[0];
    const float* rel_table  = (const float*)d_in[1];
    const float* time_table = (const float*)d_in[2];
    const float* W_rt       = (const float*)d_in[3];
    const float* b_rt       = (const float*)d_in[4];
    const float* W_fc       = (const float*)d_in[5];
    const float* b_fc       = (const float*)d_in[6];
    const int*   edges      = (const int*)d_in[7];
    float* out = (float*)d_out;

    cudaFuncSetAttribute(hmma_all, cudaFuncAttributeMaxDynamicSharedMemorySize, SM_TOTAL);

    // side stream + fork/join events (created once, before first capture)
    static cudaStream_t s1 = nullptr;
    static cudaEvent_t evFork = nullptr, evJoin = nullptr;
    if (!s1) {
        cudaStreamCreateWithFlags(&s1, cudaStreamNonBlocking);
        cudaEventCreateWithFlags(&evFork, cudaEventDisableTiming);
        cudaEventCreateWithFlags(&evJoin, cudaEventDisableTiming);
    }

    // ---- fork: sort chain on side stream, GEMM chain on main ----
    // d_counts is zero on entry (zero-init at load; re-zeroed by k_scanfin).
    cudaEventRecord(evFork, 0);
    cudaStreamWaitEvent(s1, evFork, 0);

    // kernel launch order (ncu -s 5 -c 1 profiles launch #6 = hmma_all):
    // count(1) bsum(2) scanb(3) scanfin(4) prep(5) hmma(6) scatter(7) agg(8)
    k_count<<<(NEDGES + 255) / 256, 256, 0, s1>>>(edges);
    k_bsum<<<NBLK, 256, 0, s1>>>();
    k_scanb<<<1, 256, 0, s1>>>();
    k_scanfin<<<NBLK, 256, 0, s1>>>();

    k_prep<<<NREL + NTS + 192, 256>>>(rel_table, time_table, W_rt, W_fc);
    hmma_all<<<NB0 + NB1, 256, SM_TOTAL>>>(x, b_rt);

    k_scatter<<<(NEDGES + 255) / 256, 256, 0, s1>>>(edges);
    cudaEventRecord(evJoin, s1);

    // ---- join: aggregation needs both chains ----
    cudaStreamWaitEvent(0, evJoin, 0);
    k_agg<<<(NNODES * 32 + 255) / 256, 256>>>(out, b_fc);
}